// round 17
// baseline (speedup 1.0000x reference)
#include <cuda_runtime.h>
#include <cuda_bf16.h>
#include <cstdint>

#define BB 8
#define CC 64
#define NN 4096
#define KK 16
#define EE 64
#define NPOINTS (BB*NN)            // 32768
#define CNT1 524288.0f             // B*N*K
#define CNT3 32768.0f              // B*N
#define EPSV 1e-5f

// ---- scratch (device globals: allocation-free rule) ----
// g_y1t holds y1 in PERMUTED channel layout: phys float4 slot (blk, q) holds
// orig channels {blk*16+2q, +1, blk*16+2q+8, +9}
__device__ float g_y1t[NPOINTS*EE];       // 8 MB
__device__ float g_zmax[NPOINTS*EE];      // 8 MB
__device__ float g_zmin[NPOINTS*EE];      // 8 MB
__device__ float g_sum1[EE], g_sumsq1[EE];   // PHYS channel order
__device__ float g_sum2[EE], g_sumsq2[EE];
__device__ float g_bs3[32][128];          // BN3 bucketed partials

// pack two fp32 into bf16x2 (first arg -> low half)
__device__ __forceinline__ uint32_t pack_bf2(float lo_e, float hi_e) {
    uint32_t r;
    asm("cvt.rn.bf16x2.f32 %0, %1, %2;" : "=r"(r) : "f"(hi_e), "f"(lo_e));
    return r;
}

__device__ __forceinline__ void mma16816(float d[4], const uint32_t a[4], uint32_t b0, uint32_t b1) {
    asm volatile(
        "mma.sync.aligned.m16n8k16.row.col.f32.bf16.bf16.f32 "
        "{%0,%1,%2,%3}, {%4,%5,%6,%7}, {%8,%9}, {%0,%1,%2,%3};"
        : "+f"(d[0]), "+f"(d[1]), "+f"(d[2]), "+f"(d[3])
        : "r"(a[0]), "r"(a[1]), "r"(a[2]), "r"(a[3]), "r"(b0), "r"(b1));
}

// split a packed pair (x,y) into hi (bf16) and lo (residual bf16)
__device__ __forceinline__ void split2(float x, float y, uint32_t& hi, uint32_t& lo) {
    hi = pack_bf2(x, y);
    float e0 = __uint_as_float(hi << 16);
    float e1 = __uint_as_float(hi & 0xffff0000u);
    lo = pack_bf2(x - e0, y - e1);
}

__device__ __forceinline__ uint32_t smem_u32(const void* p) {
    uint32_t a;
    asm("{ .reg .u64 t; cvta.to.shared.u64 t, %1; cvt.u32.u64 %0, t; }" : "=r"(a) : "l"(p));
    return a;
}
__device__ __forceinline__ float4 lds128(uint32_t a) {
    float4 v;
    asm volatile("ld.shared.v4.f32 {%0,%1,%2,%3}, [%4];"
                 : "=f"(v.x), "=f"(v.y), "=f"(v.z), "=f"(v.w) : "r"(a));
    return v;
}
__device__ __forceinline__ uint4 lds128u(uint32_t a) {
    uint4 v;
    asm volatile("ld.shared.v4.u32 {%0,%1,%2,%3}, [%4];"
                 : "=r"(v.x), "=r"(v.y), "=r"(v.z), "=r"(v.w) : "r"(a));
    return v;
}
__device__ __forceinline__ void sts128u(uint32_t a, uint4 v) {
    asm volatile("st.shared.v4.u32 [%0], {%1,%2,%3,%4};"
                 :: "r"(a), "r"(v.x), "r"(v.y), "r"(v.z), "r"(v.w) : "memory");
}
#define CP16(d, s) asm volatile("cp.async.cg.shared.global [%0], [%1], 16;" :: "r"(d), "l"(s) : "memory")
#define CP_COMMIT() asm volatile("cp.async.commit_group;" ::: "memory")
#define CP_WAIT1()  asm volatile("cp.async.wait_group 1;" ::: "memory")

// ============================================================================
// k_y1 via mma.sync: y1[64e, 64pts] = W1 @ x_tile, stored PERMUTED point-major.
__global__ void __launch_bounds__(128) k_y1(const float* __restrict__ x,
                                            const float* __restrict__ W1) {
    __shared__ uint32_t Uhi[32*65];
    __shared__ uint32_t Ulo[32*65];
    __shared__ float sD[64*65];
    int b = blockIdx.y;
    int n0 = blockIdx.x * 64;
    int t = threadIdx.x;
    int lane = t & 31, w = t >> 5;
    int g = lane >> 2, q = lane & 3;

    if (blockIdx.x == 0 && blockIdx.y == 0) {
        if (t < EE) {
            g_sum1[t]=0.f; g_sumsq1[t]=0.f;
            g_sum2[t]=0.f; g_sumsq2[t]=0.f;
        }
        for (int i = t; i < 32*128; i += 128) ((float*)g_bs3)[i] = 0.f;
    }

    uint32_t Ahi[4][4], Alo[4][4];
    {
        int o0 = w*16 + g;
        #pragma unroll
        for (int ks = 0; ks < 4; ks++) {
            int cb = ks*16 + q*2;
            const float* r0 = W1 + o0*64 + cb;
            const float* r1 = W1 + (o0+8)*64 + cb;
            float2 a00 = *(const float2*)(r0);
            float2 a01 = *(const float2*)(r0 + 8);
            float2 a10 = *(const float2*)(r1);
            float2 a11 = *(const float2*)(r1 + 8);
            split2(a00.x, a00.y, Ahi[ks][0], Alo[ks][0]);
            split2(a10.x, a10.y, Ahi[ks][1], Alo[ks][1]);
            split2(a01.x, a01.y, Ahi[ks][2], Alo[ks][2]);
            split2(a11.x, a11.y, Ahi[ks][3], Alo[ks][3]);
        }
    }

    #pragma unroll
    for (int i4 = t; i4 < 2048; i4 += 128) {
        int c2 = i4 >> 6;
        int pt = i4 & 63;
        float xa = x[(size_t)(b*CC + 2*c2)*NN + n0 + pt];
        float xb = x[(size_t)(b*CC + 2*c2 + 1)*NN + n0 + pt];
        uint32_t h, l;
        split2(xa, xb, h, l);
        Uhi[c2*65 + pt] = h;
        Ulo[c2*65 + pt] = l;
    }
    __syncthreads();

    #pragma unroll
    for (int nt = 0; nt < 8; nt++) {
        float D[4] = {0.f, 0.f, 0.f, 0.f};
        int pt = nt*8 + g;
        #pragma unroll
        for (int ks = 0; ks < 4; ks++) {
            uint32_t bh0 = Uhi[(ks*8 + q)*65 + pt];
            uint32_t bh1 = Uhi[(ks*8 + q + 4)*65 + pt];
            uint32_t bl0 = Ulo[(ks*8 + q)*65 + pt];
            uint32_t bl1 = Ulo[(ks*8 + q + 4)*65 + pt];
            mma16816(D, Ahi[ks], bh0, bh1);
            mma16816(D, Alo[ks], bh0, bh1);
            mma16816(D, Ahi[ks], bl0, bl1);
        }
        int ch = w*16 + g;
        int pc = nt*8 + q*2;
        sD[ch*65 + pc]     = D[0];
        sD[ch*65 + pc + 1] = D[1];
        sD[(ch+8)*65 + pc]     = D[2];
        sD[(ch+8)*65 + pc + 1] = D[3];
    }
    __syncthreads();

    #pragma unroll
    for (int i = t; i < 1024; i += 128) {
        int pt = i >> 4;
        int s4 = i & 15;
        int blk = s4 >> 2, qp = s4 & 3;
        int ob = blk*16 + qp*2;
        float4 v;
        v.x = sD[ob*65 + pt];
        v.y = sD[(ob+1)*65 + pt];
        v.z = sD[(ob+8)*65 + pt];
        v.w = sD[(ob+9)*65 + pt];
        *(float4*)(g_y1t + (size_t)(b*NN + n0 + pt)*EE + s4*4) = v;
    }
}

// BN1 stats over d = y_j - y_n (permuted data -> sums in PHYS order)
__global__ void k_stats1(const int* __restrict__ idx) {
    __shared__ float4 red_s[16][16];
    __shared__ float4 red_q[16][16];
    int t = threadIdx.x;
    int c4 = t & 15, g = t >> 4;
    float4 s = make_float4(0.f,0.f,0.f,0.f);
    float4 q = make_float4(0.f,0.f,0.f,0.f);
    int p0 = blockIdx.x * 64;
    #pragma unroll 1
    for (int pl = 0; pl < 4; pl++) {
        int point = p0 + g*4 + pl;
        int brow = point & ~(NN-1);
        int jown = idx[point*KK + c4];
        float4 yn = *(const float4*)(g_y1t + (size_t)point*EE + c4*4);
        #pragma unroll
        for (int k = 0; k < KK; k++) {
            int j = __shfl_sync(0xffffffffu, jown, ((t & 31) & 16) | k, 32);
            float4 yj = *(const float4*)(g_y1t + (size_t)(brow + j)*EE + c4*4);
            float dx = yj.x - yn.x, dy = yj.y - yn.y, dz = yj.z - yn.z, dw = yj.w - yn.w;
            s.x += dx; s.y += dy; s.z += dz; s.w += dw;
            q.x = fmaf(dx, dx, q.x); q.y = fmaf(dy, dy, q.y);
            q.z = fmaf(dz, dz, q.z); q.w = fmaf(dw, dw, q.w);
        }
    }
    red_s[g][c4] = s;
    red_q[g][c4] = q;
    __syncthreads();
    if (t < 64) {
        float ss = 0.f, qq = 0.f;
        #pragma unroll
        for (int gg = 0; gg < 16; gg++) {
            ss += ((const float*)&red_s[gg][t >> 2])[t & 3];
            qq += ((const float*)&red_q[gg][t >> 2])[t & 3];
        }
        atomicAdd(&g_sum1[t], ss);
        atomicAdd(&g_sumsq1[t], qq);
    }
}

// ============================================================================
// Main pass v2: thread-local cp.async staging (cen+r0+r1 per thread, 48B),
// double-buffered fragment publish, ONE barrier per point, convert(p+1)
// overlapped with MMA(p).
#define ST_BYTES  6144                   // 128 threads x 48B
#define CONV_BASE (4*ST_BYTES)           // 24576
#define RED_OFF   (CONV_BASE + 8192)     // 32768
#define EDGE_SMEM (RED_OFF + 512)        // 33280

__device__ __forceinline__ void stage_point(uint32_t sbuf, int p, int j0, int j1,
                                            int ko, int toff) {
    int base = p & ~(NN-1);
    const char* cen = (const char*)g_y1t + (((size_t)p) << 8);
    const char* r0  = (const char*)g_y1t + (((size_t)(base + j0)) << 8);
    const char* r1  = (const char*)g_y1t + (((size_t)(base + j1)) << 8);
    CP16(sbuf + toff,      cen + ko);
    CP16(sbuf + toff + 16, r0  + ko);
    CP16(sbuf + toff + 32, r1  + ko);
    CP_COMMIT();
}

__global__ void __launch_bounds__(128, 6) k_edge(const int* __restrict__ idx,
                                                 const float* __restrict__ W2,
                                                 const float* __restrict__ g1,
                                                 const float* __restrict__ be1) {
    extern __shared__ char esm[];
    uint32_t sb = smem_u32(esm);
    float* sm_s = (float*)(esm + RED_OFF);
    float* sm_q = sm_s + 64;
    int t = threadIdx.x;
    int lane = t & 31, w = t >> 5;
    int g = lane >> 2, q = lane & 3;
    int ko = w*64 + q*16;
    int toff = t*48;

    if (t < 64) { sm_s[t] = 0.f; sm_q[t] = 0.f; }

    // BN1 fold for this thread's 4 phys channels
    float a1v[4], c1v[4];
    #pragma unroll
    for (int j = 0; j < 4; j++) {
        int phys = w*16 + q*4 + j;
        int orig = w*16 + ((j < 2) ? (q*2 + j) : (q*2 + 8 + (j - 2)));
        float m1 = g_sum1[phys] * (1.f/CNT1);
        float v1 = fmaxf(g_sumsq1[phys] * (1.f/CNT1) - m1*m1, 0.f);
        a1v[j] = g1[orig] * rsqrtf(v1 + EPSV);
        c1v[j] = be1[orig] - a1v[j] * m1;
    }

    // A = W2 fragments for this warp's single m-tile
    uint32_t Ahi[4][4], Alo[4][4];
    {
        int o0 = w*16 + g;
        #pragma unroll
        for (int ks = 0; ks < 4; ks++) {
            int cb = ks*16 + q*2;
            const float* r0 = W2 + o0*64 + cb;
            const float* r1 = W2 + (o0+8)*64 + cb;
            float2 a00 = *(const float2*)(r0);
            float2 a01 = *(const float2*)(r0 + 8);
            float2 a10 = *(const float2*)(r1);
            float2 a11 = *(const float2*)(r1 + 8);
            split2(a00.x, a00.y, Ahi[ks][0], Alo[ks][0]);
            split2(a10.x, a10.y, Ahi[ks][1], Alo[ks][1]);
            split2(a01.x, a01.y, Ahi[ks][2], Alo[ks][2]);
            split2(a11.x, a11.y, Ahi[ks][3], Alo[ks][3]);
        }
    }

    int pbase = blockIdx.x * 16;

    // convert lambda-ish macro: reads this thread's OWN staged 48B, publishes frags
#define EDGE_CONVERT(SBUF, CB) do {                                          \
        float4 nf = lds128((SBUF) + toff);                                   \
        float4 x0 = lds128((SBUF) + toff + 16);                              \
        float4 x1 = lds128((SBUF) + toff + 32);                              \
        float h00 = fmaxf(fmaf(a1v[0], x0.x - nf.x, c1v[0]), 0.f);           \
        float h01 = fmaxf(fmaf(a1v[1], x0.y - nf.y, c1v[1]), 0.f);           \
        float h02 = fmaxf(fmaf(a1v[2], x0.z - nf.z, c1v[2]), 0.f);           \
        float h03 = fmaxf(fmaf(a1v[3], x0.w - nf.w, c1v[3]), 0.f);           \
        float h10 = fmaxf(fmaf(a1v[0], x1.x - nf.x, c1v[0]), 0.f);           \
        float h11 = fmaxf(fmaf(a1v[1], x1.y - nf.y, c1v[1]), 0.f);           \
        float h12 = fmaxf(fmaf(a1v[2], x1.z - nf.z, c1v[2]), 0.f);           \
        float h13 = fmaxf(fmaf(a1v[3], x1.w - nf.w, c1v[3]), 0.f);           \
        uint32_t bh00, bl00, bh01, bl01, bh10, bl10, bh11, bl11;             \
        split2(h00, h01, bh00, bl00);                                        \
        split2(h02, h03, bh01, bl01);                                        \
        split2(h10, h11, bh10, bl10);                                        \
        split2(h12, h13, bh11, bl11);                                        \
        uint32_t cba = sb + CONV_BASE + (CB)*4096;                           \
        sts128u(cba + w*512 + lane*16,        make_uint4(bh00, bh01, bl00, bl01)); \
        sts128u(cba + 2048 + w*512 + lane*16, make_uint4(bh10, bh11, bl10, bl11)); \
    } while (0)

    // prologue: stage p0, p1; convert p0
    {
        int a0 = idx[(pbase+0)*KK + g], a1 = idx[(pbase+0)*KK + 8 + g];
        int b0 = idx[(pbase+1)*KK + g], b1 = idx[(pbase+1)*KK + 8 + g];
        stage_point(sb + 0*ST_BYTES, pbase+0, a0, a1, ko, toff);
        stage_point(sb + 1*ST_BYTES, pbase+1, b0, b1, ko, toff);
    }
    int j0n = idx[(pbase+2)*KK + g], j1n = idx[(pbase+2)*KK + 8 + g];
    CP_WAIT1();                      // p0 staged (own groups)
    EDGE_CONVERT(sb + 0*ST_BYTES, 0);

    float sums[2], sumq[2];
    sums[0]=0.f; sums[1]=0.f; sumq[0]=0.f; sumq[1]=0.f;

    #pragma unroll 1
    for (int pi = 0; pi < 16; pi++) {
        int p = pbase + pi;
        __syncthreads();             // conv[pi&1] visible; prior reads retired
        if (pi + 2 < 16)
            stage_point(sb + ((pi+2)&3)*ST_BYTES, p + 2, j0n, j1n, ko, toff);
        else
            CP_COMMIT();
        int pn3 = (pi + 3 < 16) ? p + 3 : pbase + 15;
        int j0f = idx[pn3*KK + g], j1f = idx[pn3*KK + 8 + g];

        if (pi + 1 < 16) {
            CP_WAIT1();              // group pi+1 complete (own thread's chunks)
            EDGE_CONVERT(sb + ((pi+1)&3)*ST_BYTES, (pi+1)&1);
        }

        float D[2][4];
        #pragma unroll
        for (int nt = 0; nt < 2; nt++)
            #pragma unroll
            for (int i = 0; i < 4; i++) D[nt][i] = 0.f;

        uint32_t cbuf = sb + CONV_BASE + (pi & 1)*4096;
        #pragma unroll
        for (int ks = 0; ks < 4; ks++) {
            uint4 fa = lds128u(cbuf + ks*512 + lane*16);
            uint4 fb = lds128u(cbuf + 2048 + ks*512 + lane*16);
            mma16816(D[0], Ahi[ks], fa.x, fa.y);
            mma16816(D[0], Alo[ks], fa.x, fa.y);
            mma16816(D[0], Ahi[ks], fa.z, fa.w);
            mma16816(D[1], Ahi[ks], fb.x, fb.y);
            mma16816(D[1], Alo[ks], fb.x, fb.y);
            mma16816(D[1], Ahi[ks], fb.z, fb.w);
        }

        // reduce over neighbors: in-thread, then shfl over q
        {
            float d00 = D[0][0], d01 = D[0][1];
            float d10 = D[1][0], d11 = D[1][1];
            float e00 = D[0][2], e01 = D[0][3];
            float e10 = D[1][2], e11 = D[1][3];
            sums[0] += (d00 + d01) + (d10 + d11);
            sums[1] += (e00 + e01) + (e10 + e11);
            sumq[0] = fmaf(d00,d00, fmaf(d01,d01, fmaf(d10,d10, fmaf(d11,d11, sumq[0]))));
            sumq[1] = fmaf(e00,e00, fmaf(e01,e01, fmaf(e10,e10, fmaf(e11,e11, sumq[1]))));
            float mx0 = fmaxf(fmaxf(d00, d01), fmaxf(d10, d11));
            float mn0 = fminf(fminf(d00, d01), fminf(d10, d11));
            float mx1 = fmaxf(fmaxf(e00, e01), fmaxf(e10, e11));
            float mn1 = fminf(fminf(e00, e01), fminf(e10, e11));
            #pragma unroll
            for (int off = 1; off < 4; off <<= 1) {
                mx0 = fmaxf(mx0, __shfl_xor_sync(0xffffffffu, mx0, off));
                mn0 = fminf(mn0, __shfl_xor_sync(0xffffffffu, mn0, off));
                mx1 = fmaxf(mx1, __shfl_xor_sync(0xffffffffu, mx1, off));
                mn1 = fminf(mn1, __shfl_xor_sync(0xffffffffu, mn1, off));
            }
            if (q == 0) {
                int ch = w*16 + g;
                g_zmax[(size_t)p*EE + ch]     = mx0;
                g_zmax[(size_t)p*EE + ch + 8] = mx1;
                g_zmin[(size_t)p*EE + ch]     = mn0;
                g_zmin[(size_t)p*EE + ch + 8] = mn1;
            }
        }
        j0n = j0f; j1n = j1f;
    }
#undef EDGE_CONVERT

    // BN2 sums: shfl-reduce over q, stage in smem, one global atomic per channel
    #pragma unroll
    for (int i = 0; i < 2; i++) {
        float s = sums[i], qq = sumq[i];
        #pragma unroll
        for (int off = 1; off < 4; off <<= 1) {
            s  += __shfl_xor_sync(0xffffffffu, s, off);
            qq += __shfl_xor_sync(0xffffffffu, qq, off);
        }
        if (q == 0) {
            int ch = w*16 + g + i*8;
            atomicAdd(&sm_s[ch], s);
            atomicAdd(&sm_q[ch], qq);
        }
    }
    __syncthreads();
    if (t < 64) {
        atomicAdd(&g_sum2[t],   sm_s[t]);
        atomicAdd(&g_sumsq2[t], sm_q[t]);
    }
}

// ============================================================================
// pool3 via mma.sync, 256 threads: 8 warps, warp w owns m-tile (w&3) for
// point-half (w>>2). Same math as r16.
__global__ void __launch_bounds__(256) k_pool3(const float* __restrict__ W3,
                                               const float* __restrict__ g2,
                                               const float* __restrict__ be2,
                                               float* __restrict__ out) {
    __shared__ uint32_t Uhi[32*65];
    __shared__ uint32_t Ulo[32*65];
    __shared__ float a2s[64], c2s[64];
    int b = blockIdx.y;
    int n0 = blockIdx.x * 64;
    int t = threadIdx.x;
    int lane = t & 31, w = t >> 5;
    int mt = w & 3, ph = w >> 2;
    int g = lane >> 2, q = lane & 3;

    if (t < 64) {
        float m2 = g_sum2[t] * (1.f/CNT1);
        float v2 = fmaxf(g_sumsq2[t] * (1.f/CNT1) - m2*m2, 0.f);
        float a2o = g2[t] * rsqrtf(v2 + EPSV);
        a2s[t] = a2o;
        c2s[t] = be2[t] - a2o * m2;
    }

    uint32_t Ahi[4][4], Alo[4][4];
    {
        int o0 = mt*16 + g;
        #pragma unroll
        for (int ks = 0; ks < 4; ks++) {
            int cb = ks*16 + q*2;
            const float* r0 = W3 + o0*64 + cb;
            const float* r1 = W3 + (o0+8)*64 + cb;
            float2 a00 = *(const float2*)(r0);
            float2 a01 = *(const float2*)(r0 + 8);
            float2 a10 = *(const float2*)(r1);
            float2 a11 = *(const float2*)(r1 + 8);
            split2(a00.x, a00.y, Ahi[ks][0], Alo[ks][0]);
            split2(a10.x, a10.y, Ahi[ks][1], Alo[ks][1]);
            split2(a01.x, a01.y, Ahi[ks][2], Alo[ks][2]);
            split2(a11.x, a11.y, Ahi[ks][3], Alo[ks][3]);
        }
    }
    __syncthreads();

    {
        const float4* zmx4 = (const float4*)(g_zmax + (size_t)(b*NN + n0)*EE);
        const float4* zmn4 = (const float4*)(g_zmin + (size_t)(b*NN + n0)*EE);
        #pragma unroll
        for (int i4 = t; i4 < 1024; i4 += 256) {
            int pt = i4 >> 4;
            int c4 = i4 & 15;
            int c0 = c4 * 4;
            float4 zx = zmx4[i4];
            float4 zn = zmn4[i4];
            float a0 = a2s[c0],   cc0 = c2s[c0];
            float a1 = a2s[c0+1], cc1 = c2s[c0+1];
            float a2 = a2s[c0+2], cc2 = c2s[c0+2];
            float a3 = a2s[c0+3], cc3 = c2s[c0+3];
            float m0 = fmaxf(fmaf(a0, (a0 >= 0.f) ? zx.x : zn.x, cc0), 0.f);
            float m1 = fmaxf(fmaf(a1, (a1 >= 0.f) ? zx.y : zn.y, cc1), 0.f);
            float m2 = fmaxf(fmaf(a2, (a2 >= 0.f) ? zx.z : zn.z, cc2), 0.f);
            float m3 = fmaxf(fmaf(a3, (a3 >= 0.f) ? zx.w : zn.w, cc3), 0.f);
            uint32_t h0, l0, h1, l1;
            split2(m0, m1, h0, l0);
            split2(m2, m3, h1, l1);
            int c2a = c4 * 2;
            Uhi[c2a*65 + pt]     = h0;
            Uhi[(c2a+1)*65 + pt] = h1;
            Ulo[c2a*65 + pt]     = l0;
            Ulo[(c2a+1)*65 + pt] = l1;
        }
    }
    __syncthreads();

    int bucket = (blockIdx.y * 64 + blockIdx.x) & 31;
    float sums[2], sumq[2];
    sums[0]=0.f; sums[1]=0.f; sumq[0]=0.f; sumq[1]=0.f;

    #pragma unroll
    for (int nt = 0; nt < 4; nt++) {
        float D[4] = {0.f, 0.f, 0.f, 0.f};
        int pt = ph*32 + nt*8 + g;
        #pragma unroll
        for (int ks = 0; ks < 4; ks++) {
            uint32_t bh0 = Uhi[(ks*8 + q)*65 + pt];
            uint32_t bh1 = Uhi[(ks*8 + q + 4)*65 + pt];
            uint32_t bl0 = Ulo[(ks*8 + q)*65 + pt];
            uint32_t bl1 = Ulo[(ks*8 + q + 4)*65 + pt];
            mma16816(D, Ahi[ks], bh0, bh1);
            mma16816(D, Alo[ks], bh0, bh1);
            mma16816(D, Ahi[ks], bl0, bl1);
        }
        int ch = mt*16 + g;
        int pcol = n0 + ph*32 + nt*8 + q*2;
        *(float2*)(out + (size_t)(b*EE + ch)*NN + pcol)     = make_float2(D[0], D[1]);
        *(float2*)(out + (size_t)(b*EE + ch + 8)*NN + pcol) = make_float2(D[2], D[3]);
        sums[0] += D[0] + D[1];
        sums[1] += D[2] + D[3];
        sumq[0] = fmaf(D[0],D[0], fmaf(D[1],D[1], sumq[0]));
        sumq[1] = fmaf(D[2],D[2], fmaf(D[3],D[3], sumq[1]));
    }

    #pragma unroll
    for (int i = 0; i < 2; i++) {
        float s = sums[i], qv = sumq[i];
        #pragma unroll
        for (int off = 1; off < 4; off <<= 1) {
            s  += __shfl_xor_sync(0xffffffffu, s, off);
            qv += __shfl_xor_sync(0xffffffffu, qv, off);
        }
        if (q == 0) {
            int ch = mt*16 + g + i*8;
            atomicAdd(&g_bs3[bucket][ch], s);
            atomicAdd(&g_bs3[bucket][64 + ch], qv);
        }
    }
}

// BN3 + ReLU in place (folds the 32 buckets first)
__global__ void k_out(const float* __restrict__ g3, const float* __restrict__ be3,
                      float* __restrict__ out) {
    __shared__ float sa[EE], sc[EE];
    int t = threadIdx.x;
    if (t < EE) {
        float s = 0.f, qv = 0.f;
        #pragma unroll
        for (int bk = 0; bk < 32; bk++) {
            s  += g_bs3[bk][t];
            qv += g_bs3[bk][64 + t];
        }
        float m3 = s * (1.f/CNT3);
        float v3 = fmaxf(qv * (1.f/CNT3) - m3*m3, 0.f);
        float a3 = g3[t] * rsqrtf(v3 + EPSV);
        sa[t] = a3;
        sc[t] = be3[t] - a3 * m3;
    }
    __syncthreads();
    int gi = blockIdx.x * blockDim.x + t;
    int o = (gi >> 10) & 63;
    float4* out4 = (float4*)out;
    float4 v = out4[gi];
    float a = sa[o], c = sc[o];
    v.x = fmaxf(fmaf(a, v.x, c), 0.f);
    v.y = fmaxf(fmaf(a, v.y, c), 0.f);
    v.z = fmaxf(fmaf(a, v.z, c), 0.f);
    v.w = fmaxf(fmaf(a, v.w, c), 0.f);
    out4[gi] = v;
}

extern "C" void kernel_launch(void* const* d_in, const int* in_sizes, int n_in,
                              void* d_out, int out_size) {
    const float* x   = (const float*)d_in[0];
    const int*   idx = (const int*)  d_in[1];
    const float* W1  = (const float*)d_in[2];
    const float* g1  = (const float*)d_in[4];
    const float* be1 = (const float*)d_in[5];
    const float* W2  = (const float*)d_in[6];
    const float* g2  = (const float*)d_in[8];
    const float* be2 = (const float*)d_in[9];
    const float* W3  = (const float*)d_in[10];
    const float* g3  = (const float*)d_in[12];
    const float* be3 = (const float*)d_in[13];
    float* out = (float*)d_out;

    cudaFuncSetAttribute(k_edge, cudaFuncAttributeMaxDynamicSharedMemorySize, EDGE_SMEM);

    k_y1    <<<dim3(64, 8), 128>>>(x, W1);
    k_stats1<<<512, 256>>>(idx);
    k_edge  <<<2048, 128, EDGE_SMEM>>>(idx, W2, g1, be1);
    k_pool3 <<<dim3(64, 8), 256>>>(W3, g2, be2, out);
    k_out   <<<2048, 256>>>(g3, be3, out);
}